// round 6
// baseline (speedup 1.0000x reference)
#include <cuda_runtime.h>
#include <math.h>

#define L    48
#define LH   26
#define N3   110592
#define NHALF 55296
#define BF   128
#define CF   256
#define PLH  59904              // 48*48*26

typedef unsigned long long u64;
__device__ __forceinline__ u64 pk2(float lo, float hi) {
    u64 r; asm("mov.b64 %0,{%1,%2};" : "=l"(r) : "f"(lo), "f"(hi)); return r;
}
__device__ __forceinline__ float2 up2(u64 v) {
    float2 f; asm("mov.b64 {%0,%1},%2;" : "=f"(f.x), "=f"(f.y) : "l"(v)); return f;
}
__device__ __forceinline__ void fma2(u64& d, u64 a, u64 b) {
    asm("fma.rn.f32x2 %0,%1,%2,%0;" : "+l"(d) : "l"(a), "l"(b));
}
__device__ __forceinline__ u64 mul2(u64 a, u64 b) {
    u64 d; asm("mul.rn.f32x2 %0,%1,%2;" : "=l"(d) : "l"(a), "l"(b)); return d;
}

// ---------------- scratch ----------------------------------------------------
__device__ float2 g_tw[L * L];
__device__ float2 g_tw1[L];
__device__ float2 g_emp[L];
__device__ float  g_bufR[BF * PLH];
__device__ float  g_bufI[BF * PLH];
__device__ float  g_Xh[BF * N3];
__device__ float  g_Yh[CF * N3];
__device__ float  g_Z [BF * N3];
__device__ float2 g_T1[CF * 12 * 12 * L];
__device__ float2 g_T2[CF * 12 * L * L];

// ---------------- twiddle init ----------------------------------------------
__global__ void init_tw() {
    int idx = blockIdx.x * blockDim.x + threadIdx.x;
    if (idx < L * L) {
        int k = idx / L, n = idx % L;
        int m = (k * n) % L;
        double a = -6.283185307179586476925286766559 * (double)m / (double)L;
        g_tw[idx] = make_float2((float)cos(a), (float)sin(a));
    }
    if (idx < L) {
        double a = -6.283185307179586476925286766559 * (double)idx / (double)L;
        float cx = (float)cos(a), cy = (float)sin(a);
        g_tw1[idx] = make_float2(cx, cy);
        g_emp[idx] = make_float2(cx - cy, cx + cy);
    }
}

// ============ fused pass W+H (packed f32x2, SoA smem) =======================
// block = (field, d). out SoA [f][d][k_h][k_w], k_w in [0,26)
__global__ __launch_bounds__(256) void pass_wh(
    const float* __restrict__ in, float* __restrict__ outR, float* __restrict__ outI)
{
    __shared__ __align__(16) char ubuf[2 * 48 * 28 * 4];          // P overlay Cr/Ci
    float (*P)[50]  = reinterpret_cast<float(*)[50]>(ubuf);       // 9600B <= 10752B
    float (*Cr)[28] = reinterpret_cast<float(*)[28]>(ubuf);
    float (*Ci)[28] = reinterpret_cast<float(*)[28]>(ubuf + 48 * 28 * 4);
    __shared__ __align__(16) float Ar[48][50], Ai[48][50];
    __shared__ __align__(16) float Br[48][28], Bi[48][28];        // [h][k_w]
    __shared__ u64 Cc[48], Ss[48], Sn[48];
    __shared__ float2 TWs[48];

    int t = threadIdx.x;
    int f = blockIdx.x / 48, d = blockIdx.x % 48;
    const float* src = in + (size_t)f * N3 + (size_t)d * 2304;

    if (t < 48) {
        float2 w = g_tw1[t];
        TWs[t] = w;
        Cc[t] = pk2(w.x, w.x);  Ss[t] = pk2(w.y, w.y);  Sn[t] = pk2(-w.y, -w.y);
    }
    for (int idx = t; idx < 2304; idx += 256)
        P[idx % 48][idx / 48] = src[idx];                          // P[w][h]
    __syncthreads();

    int tx = t & 15, ty = t >> 4;
    int k1 = ty & 7;
    bool g1 = (tx < 10);
    bool tp = (tx < 13);

    // ---- stage 1 (w, real): A[m][h], j = h pairs {2tx,2tx+1} + single 32+tx
    {
        u64 r01[3] = {0,0,0}, i01[3] = {0,0,0};
        float rs[3] = {0,0,0}, is[3] = {0,0,0};
        int step = (6 * k1) % 48, widx = 0;
        #pragma unroll
        for (int n1 = 0; n1 < 8; n1++) {
            u64 cc = Cc[widx], ss = Ss[widx];
            float2 w = TWs[widx];
            widx += step; if (widx >= 48) widx -= 48;
            #pragma unroll
            for (int a = 0; a < 3; a++) {
                int row = 6 * n1 + ((ty + 16 * a) >> 3);
                u64 p01 = *(const u64*)&P[row][2 * tx];
                float ps = P[row][32 + tx];
                fma2(r01[a], p01, cc);  fma2(i01[a], p01, ss);
                rs[a] += ps * w.x;  is[a] += ps * w.y;
            }
        }
        #pragma unroll
        for (int a = 0; a < 3; a++) {
            int m = ty + 16 * a;
            *(u64*)&Ar[m][2 * tx] = r01[a];
            *(u64*)&Ai[m][2 * tx] = i01[a];
            Ar[m][32 + tx] = rs[a];  Ai[m][32 + tx] = is[a];
        }
    }
    __syncthreads();

    // ---- stage 2 (w): k_w = tx + 16c, j = h pairs {2ty,2ty+1} + single 32+ty
    {
        u64 r01[2] = {0,0}, i01[2] = {0,0};
        float rs[2] = {0,0}, is[2] = {0,0};
        int r8 = tx & 7;
        int i0 = 0, i1 = 0;
        int kwa = tx, kwb = tx + 16;
        #pragma unroll
        for (int n2 = 0; n2 < 6; n2++) {
            int arow = n2 * 8 + r8;
            u64 xr01 = *(const u64*)&Ar[arow][2 * ty];
            u64 xi01 = *(const u64*)&Ai[arow][2 * ty];
            float xrs = Ar[arow][32 + ty], xis = Ai[arow][32 + ty];
            {
                u64 cc = Cc[i0], ss = Ss[i0], sn = Sn[i0];
                float2 w = TWs[i0];
                i0 += kwa; if (i0 >= 48) i0 -= 48;
                fma2(r01[0], xr01, cc);  fma2(r01[0], xi01, sn);
                fma2(i01[0], xr01, ss);  fma2(i01[0], xi01, cc);
                rs[0] += xrs * w.x - xis * w.y;  is[0] += xrs * w.y + xis * w.x;
            }
            if (g1) {
                u64 cc = Cc[i1], ss = Ss[i1], sn = Sn[i1];
                float2 w = TWs[i1];
                fma2(r01[1], xr01, cc);  fma2(r01[1], xi01, sn);
                fma2(i01[1], xr01, ss);  fma2(i01[1], xi01, cc);
                rs[1] += xrs * w.x - xis * w.y;  is[1] += xrs * w.y + xis * w.x;
            }
            i1 += kwb; if (i1 >= 48) i1 -= 48;
        }
        __syncthreads();      // all stage-2 reads of A done before B overwrites? (B separate; sync orders B-writes vs stage-3 reads)
        float2 v;
        v = up2(r01[0]); Br[2 * ty][kwa] = v.x; Br[2 * ty + 1][kwa] = v.y;
        v = up2(i01[0]); Bi[2 * ty][kwa] = v.x; Bi[2 * ty + 1][kwa] = v.y;
        Br[32 + ty][kwa] = rs[0];  Bi[32 + ty][kwa] = is[0];
        if (g1) {
            v = up2(r01[1]); Br[2 * ty][kwb] = v.x; Br[2 * ty + 1][kwb] = v.y;
            v = up2(i01[1]); Bi[2 * ty][kwb] = v.x; Bi[2 * ty + 1][kwb] = v.y;
            Br[32 + ty][kwb] = rs[1];  Bi[32 + ty][kwb] = is[1];
        }
    }
    __syncthreads();

    // ---- stage 3 (h): C[m_h][k_w], k = ty+16a, j = k_w pairs (tx<13)
    {
        u64 r01[3] = {0,0,0}, i01[3] = {0,0,0};
        int step = (6 * k1) % 48, widx = 0;
        #pragma unroll
        for (int n1 = 0; n1 < 8; n1++) {
            u64 cc = Cc[widx], ss = Ss[widx], sn = Sn[widx];
            widx += step; if (widx >= 48) widx -= 48;
            if (tp) {
                #pragma unroll
                for (int a = 0; a < 3; a++) {
                    int row = 6 * n1 + ((ty + 16 * a) >> 3);
                    u64 xr = *(const u64*)&Br[row][2 * tx];
                    u64 xi = *(const u64*)&Bi[row][2 * tx];
                    fma2(r01[a], xr, cc);  fma2(r01[a], xi, sn);
                    fma2(i01[a], xr, ss);  fma2(i01[a], xi, cc);
                }
            }
        }
        __syncthreads();      // ubuf (P) long dead; barrier orders C-writes for stage 4
        if (tp) {
            #pragma unroll
            for (int a = 0; a < 3; a++) {
                *(u64*)&Cr[ty + 16 * a][2 * tx] = r01[a];
                *(u64*)&Ci[ty + 16 * a][2 * tx] = i01[a];
            }
        }
    }
    __syncthreads();

    // ---- stage 4 (h): out[k_h][k_w]
    {
        u64 r01[3] = {0,0,0}, i01[3] = {0,0,0};
        int r8 = ty & 7;
        int iw[3] = {0, 0, 0};
        #pragma unroll
        for (int n2 = 0; n2 < 6; n2++) {
            int arow = n2 * 8 + r8;
            u64 xr = 0, xi = 0;
            if (tp) { xr = *(const u64*)&Cr[arow][2 * tx]; xi = *(const u64*)&Ci[arow][2 * tx]; }
            #pragma unroll
            for (int a = 0; a < 3; a++) {
                u64 cc = Cc[iw[a]], ss = Ss[iw[a]], sn = Sn[iw[a]];
                iw[a] += ty + 16 * a; if (iw[a] >= 48) iw[a] -= 48;
                fma2(r01[a], xr, cc);  fma2(r01[a], xi, sn);
                fma2(i01[a], xr, ss);  fma2(i01[a], xi, cc);
            }
        }
        if (tp) {
            size_t base = (size_t)(f * 48 + d) * (48 * 26);
            #pragma unroll
            for (int a = 0; a < 3; a++) {
                size_t o = base + (size_t)(ty + 16 * a) * 26 + 2 * tx;
                *(u64*)&outR[o] = r01[a];
                *(u64*)&outI[o] = i01[a];
            }
        }
    }
}

// ============ pass D (packed): DFT along d + fold + mirror ==================
__global__ __launch_bounds__(256) void pass_d(
    const float* __restrict__ inR, const float* __restrict__ inI,
    float* __restrict__ out, float scale)
{
    __shared__ __align__(16) float Qr[48][28], Qi[48][28];
    __shared__ __align__(16) float Ar[48][28], Ai[48][28];
    __shared__ u64 Cc[48], Ss[48], Sn[48];

    int t = threadIdx.x;
    int f = blockIdx.x / 48, k2 = blockIdx.x % 48;
    if (t < 48) {
        float2 w = g_tw1[t];
        Cc[t] = pk2(w.x, w.x);  Ss[t] = pk2(w.y, w.y);  Sn[t] = pk2(-w.y, -w.y);
    }
    size_t sbase = ((size_t)f * 2304 + k2) * 26;
    for (int idx = t; idx < 48 * 26; idx += 256) {
        int row = idx / 26, col = idx % 26;
        size_t g = sbase + (size_t)row * (48 * 26) + col;
        Qr[row][col] = inR[g];  Qi[row][col] = inI[g];
    }
    __syncthreads();

    int tx = t & 15, ty = t >> 4;
    bool tp = (tx < 13);
    int k1 = ty & 7;

    // ---- stage 1
    {
        u64 r01[3] = {0,0,0}, i01[3] = {0,0,0};
        int step = (6 * k1) % 48, widx = 0;
        #pragma unroll
        for (int n1 = 0; n1 < 8; n1++) {
            u64 cc = Cc[widx], ss = Ss[widx], sn = Sn[widx];
            widx += step; if (widx >= 48) widx -= 48;
            if (tp) {
                #pragma unroll
                for (int a = 0; a < 3; a++) {
                    int row = 6 * n1 + ((ty + 16 * a) >> 3);
                    u64 xr = *(const u64*)&Qr[row][2 * tx];
                    u64 xi = *(const u64*)&Qi[row][2 * tx];
                    fma2(r01[a], xr, cc);  fma2(r01[a], xi, sn);
                    fma2(i01[a], xr, ss);  fma2(i01[a], xi, cc);
                }
            }
        }
        if (tp) {
            #pragma unroll
            for (int a = 0; a < 3; a++) {
                *(u64*)&Ar[ty + 16 * a][2 * tx] = r01[a];
                *(u64*)&Ai[ty + 16 * a][2 * tx] = i01[a];
            }
        }
    }
    __syncthreads();

    // ---- stage 2 + fold/mirror
    {
        u64 r01[3] = {0,0,0}, i01[3] = {0,0,0};
        int r8 = ty & 7;
        int iw[3] = {0, 0, 0};
        #pragma unroll
        for (int n2 = 0; n2 < 6; n2++) {
            int arow = n2 * 8 + r8;
            u64 xr = 0, xi = 0;
            if (tp) { xr = *(const u64*)&Ar[arow][2 * tx]; xi = *(const u64*)&Ai[arow][2 * tx]; }
            #pragma unroll
            for (int a = 0; a < 3; a++) {
                u64 cc = Cc[iw[a]], ss = Ss[iw[a]], sn = Sn[iw[a]];
                iw[a] += ty + 16 * a; if (iw[a] >= 48) iw[a] -= 48;
                fma2(r01[a], xr, cc);  fma2(r01[a], xi, sn);
                fma2(i01[a], xr, ss);  fma2(i01[a], xi, cc);
            }
        }
        if (tp) {
            u64 SC = pk2(scale, scale), NEG1 = pk2(-1.f, -1.f), ONE1 = pk2(1.f, 1.f);
            int mk2 = (k2 == 0) ? 0 : 48 - k2;
            float* dstD = out + (size_t)f * N3 + (size_t)k2 * 48;
            float* dstM = out + (size_t)f * N3 + (size_t)mk2 * 48;
            #pragma unroll
            for (int a = 0; a < 3; a++) {
                int kd = ty + 16 * a;
                int mkd = (kd == 0) ? 0 : 48 - kd;
                u64 D = r01[a]; fma2(D, i01[a], NEG1); D = mul2(D, SC);
                u64 M = r01[a]; fma2(M, i01[a], ONE1); M = mul2(M, SC);
                *(u64*)&dstD[(size_t)kd * 2304 + 2 * tx] = D;
                float2 mv = up2(M);
                if (tx == 0) {
                    dstM[(size_t)mkd * 2304 + 0]  = mv.x;
                    dstM[(size_t)mkd * 2304 + 47] = mv.y;
                } else {
                    dstM[(size_t)mkd * 2304 + 48 - 2 * tx] = mv.x;
                    dstM[(size_t)mkd * 2304 + 47 - 2 * tx] = mv.y;
                }
            }
        }
    }
}

// ---------------- Y path -----------------------------------------------------
__global__ void ykernel1(const float* __restrict__ w) {
    int idx = blockIdx.x * blockDim.x + threadIdx.x;
    if (idx >= CF * 12 * 12 * L) return;
    int k3 = idx % L;
    int r  = idx / L;
    const float* wp = w + r * 12;
    float ar = 0.f, ai = 0.f;
    #pragma unroll
    for (int n3 = 0; n3 < 12; n3++) {
        float2 e = g_tw[k3 * L + n3];
        float  v = wp[n3];
        ar += v * e.x;  ai += v * e.y;
    }
    g_T1[idx] = make_float2(ar, ai);
}

__global__ void ykernel2() {
    int idx = blockIdx.x * blockDim.x + threadIdx.x;
    if (idx >= CF * 12 * L * L) return;
    int k3 = idx % L;
    int k2 = (idx / L) % L;
    int r  = idx / (L * L);
    float ar = 0.f, ai = 0.f;
    #pragma unroll
    for (int n2 = 0; n2 < 12; n2++) {
        float2 tv = g_T1[(r * 12 + n2) * L + k3];
        float2 e  = g_tw[k2 * L + n2];
        ar += tv.x * e.x - tv.y * e.y;
        ai += tv.x * e.y + tv.y * e.x;
    }
    g_T2[idx] = make_float2(ar, ai);
}

__global__ __launch_bounds__(256) void ykernel3t() {
    __shared__ __align__(16) float Tr[12][50], Ti[12][50];
    __shared__ u64 E1[48], E2n[48];
    __shared__ float2 EMPs[48];
    int t  = threadIdx.x;
    int io = blockIdx.x / 48, k2 = blockIdx.x % 48;

    if (t < 48) {
        float2 e = g_emp[t];
        EMPs[t] = e;  E1[t] = pk2(e.x, e.x);  E2n[t] = pk2(-e.y, -e.y);
    }
    for (int idx = t; idx < 576; idx += 256) {
        int n1 = idx / 48, c = idx % 48;
        float2 v = g_T2[(size_t)((io * 12 + n1) * 48 + k2) * 48 + c];
        Tr[n1][c] = v.x;  Ti[n1][c] = v.y;
    }
    __syncthreads();

    int tx = t & 15, ty = t >> 4;
    u64 acc01[3] = {0,0,0};
    float accs[3] = {0,0,0};
    int iw[3] = {0, 0, 0};
    #pragma unroll
    for (int n1 = 0; n1 < 12; n1++) {
        u64 xr = *(const u64*)&Tr[n1][2 * tx];
        u64 xi = *(const u64*)&Ti[n1][2 * tx];
        float xrs = Tr[n1][32 + tx], xis = Ti[n1][32 + tx];
        #pragma unroll
        for (int a = 0; a < 3; a++) {
            u64 e1 = E1[iw[a]], e2 = E2n[iw[a]];
            float2 es = EMPs[iw[a]];
            iw[a] += ty + 16 * a; if (iw[a] >= 48) iw[a] -= 48;
            fma2(acc01[a], xr, e1);  fma2(acc01[a], xi, e2);
            accs[a] += xrs * es.x - xis * es.y;
        }
    }
    #pragma unroll
    for (int a = 0; a < 3; a++) {
        size_t rowb = (size_t)io * N3 + (size_t)(ty + 16 * a) * 2304 + (size_t)k2 * 48;
        *(u64*)&g_Yh[rowb + 2 * tx] = acc01[a];
        g_Yh[rowb + 32 + tx] = accs[a];
    }
}

// ---------------- coalesced paired mix ---------------------------------------
#define MK    16
#define MPIT  20
__global__ __launch_bounds__(256) void mix3() {
    extern __shared__ float sm[];
    float* Xa = sm;
    float* Xb = Xa + 128 * MPIT;
    float* Ya = Xb + 128 * MPIT;
    float* Yb = Ya + 256 * MPIT;

    int t  = threadIdx.x;
    int k0 = blockIdx.x * MK;

    for (int q = t; q < 128 * MK; q += 256) {
        int kk = q & 15, bi = q >> 4;
        int k = k0 + kk; if (k > NHALF) k = NHALF;
        int sk = (k == 0) ? 0 : (N3 - k);
        Xa[bi * MPIT + kk] = g_Xh[(size_t)bi * N3 + k];
        Xb[bi * MPIT + kk] = g_Xh[(size_t)bi * N3 + sk];
    }
    for (int q = t; q < 256 * MK; q += 256) {
        int kk = q & 15, io = q >> 4;
        int k = k0 + kk; if (k > NHALF) k = NHALF;
        int sk = (k == 0) ? 0 : (N3 - k);
        Ya[io * MPIT + kk] = g_Yh[(size_t)io * N3 + k];
        Yb[io * MPIT + kk] = g_Yh[(size_t)io * N3 + sk];
    }
    __syncthreads();

    int kh = t >> 7;
    int b  = (t >> 4) & 7;
    int o  = t & 15;

    float acc[8] = {0,0,0,0,0,0,0,0}, accs[8] = {0,0,0,0,0,0,0,0};
    #pragma unroll 4
    for (int i = 0; i < 16; i++) {
        const float* xa = Xa + (b * 16 + i) * MPIT + kh * 8;
        const float* xb = Xb + (b * 16 + i) * MPIT + kh * 8;
        const float* ya = Ya + (i * 16 + o) * MPIT + kh * 8;
        const float* yb = Yb + (i * 16 + o) * MPIT + kh * 8;
        float xk[8], xs[8], yk[8], ys[8];
        *(float4*)&xk[0] = *(const float4*)xa;  *(float4*)&xk[4] = *(const float4*)(xa + 4);
        *(float4*)&xs[0] = *(const float4*)xb;  *(float4*)&xs[4] = *(const float4*)(xb + 4);
        *(float4*)&yk[0] = *(const float4*)ya;  *(float4*)&yk[4] = *(const float4*)(ya + 4);
        *(float4*)&ys[0] = *(const float4*)yb;  *(float4*)&ys[4] = *(const float4*)(yb + 4);
        #pragma unroll
        for (int kk = 0; kk < 8; kk++) {
            float xe = 0.5f * (xk[kk] + xs[kk]);
            float xo = 0.5f * (xk[kk] - xs[kk]);
            acc[kk]  += xe * yk[kk] + xo * ys[kk];
            accs[kk] += xe * ys[kk] - xo * yk[kk];
        }
    }

    int kb = k0 + kh * 8;
    float* zrow = g_Z + (size_t)(b * 16 + o) * N3;
    if (kb + 7 <= NHALF) {
        *(float4*)(zrow + kb)     = make_float4(acc[0], acc[1], acc[2], acc[3]);
        *(float4*)(zrow + kb + 4) = make_float4(acc[4], acc[5], acc[6], acc[7]);
    } else {
        #pragma unroll
        for (int kk = 0; kk < 8; kk++)
            if (kb + kk <= NHALF) zrow[kb + kk] = acc[kk];
    }
    #pragma unroll
    for (int kk = 0; kk < 8; kk++) {
        int k = kb + kk;
        if (k >= 1 && k <= NHALF - 1) zrow[N3 - k] = accs[kk];
    }
}

// ---------------- launcher ----------------------------------------------------
extern "C" void kernel_launch(void* const* d_in, const int* in_sizes, int n_in,
                              void* d_out, int out_size) {
    (void)in_sizes; (void)n_in; (void)out_size;
    static float* bufR = nullptr;
    static float* bufI = nullptr;
    static float* xh   = nullptr;
    static float* z    = nullptr;
    if (!bufR) {
        cudaGetSymbolAddress((void**)&bufR, g_bufR);
        cudaGetSymbolAddress((void**)&bufI, g_bufI);
        cudaGetSymbolAddress((void**)&xh,   g_Xh);
        cudaGetSymbolAddress((void**)&z,    g_Z);
        cudaFuncSetAttribute(mix3, cudaFuncAttributeMaxDynamicSharedMemorySize,
                             (128 * MPIT * 2 + 256 * MPIT * 2) * (int)sizeof(float));
    }
    const float* x  = (const float*)d_in[0];   // [8,16,48,48,48]
    const float* wt = (const float*)d_in[2];   // [16,16,12,12,12]
    float* out = (float*)d_out;

    const int mix_smem = (128 * MPIT * 2 + 256 * MPIT * 2) * (int)sizeof(float);
    const int mix_grid = NHALF / MK + 1;

    init_tw<<<(L * L + 255) / 256, 256>>>();

    ykernel1<<<(CF * 12 * 12 * L + 255) / 256, 256>>>(wt);
    ykernel2<<<(CF * 12 * L * L  + 255) / 256, 256>>>();
    ykernel3t<<<CF * L, 256>>>();

    // forward: x -> Xh
    pass_wh<<<BF * L, 256>>>(x, bufR, bufI);
    pass_d <<<BF * L, 256>>>(bufR, bufI, xh, 1.f);

    mix3<<<mix_grid, 256, mix_smem>>>();

    // inverse: Z -> out (scaled 1/N3)
    pass_wh<<<BF * L, 256>>>(z, bufR, bufI);
    pass_d <<<BF * L, 256>>>(bufR, bufI, out, 1.f / (float)N3);
}

// round 7
// speedup vs baseline: 1.1048x; 1.1048x over previous
#include <cuda_runtime.h>
#include <math.h>

#define L    48
#define LH   26                 // kept frequencies (Hermitian half: 0..25)
#define N3   110592             // 48^3
#define NHALF 55296             // N3/2
#define BF   128                // B*CIN  fields for x / Z
#define CF   256                // CIN*COUT fields for Y
#define PLH  59904              // 48*48*26

// ---------------- scratch (static device memory) ---------------------------
__device__ float2 g_tw[L * L];
__device__ float2 g_tw1[L];
__device__ float2 g_emp[L];
__device__ float2 g_bufB[BF * PLH];            // 61 MB intermediate
__device__ float  g_Xh[BF * N3];
__device__ float  g_Yh[CF * N3];
__device__ float  g_Z [BF * N3];
__device__ float2 g_T1[CF * 12 * 12 * L];

// ---------------- twiddle init ---------------------------------------------
__global__ void init_tw() {
    int idx = blockIdx.x * blockDim.x + threadIdx.x;
    if (idx < L * L) {
        int k = idx / L, n = idx % L;
        int m = (k * n) % L;
        double a = -6.283185307179586476925286766559 * (double)m / (double)L;
        g_tw[idx] = make_float2((float)cos(a), (float)sin(a));
    }
    if (idx < L) {
        double a = -6.283185307179586476925286766559 * (double)idx / (double)L;
        float cx = (float)cos(a), cy = (float)sin(a);
        g_tw1[idx] = make_float2(cx, cy);
        g_emp[idx] = make_float2(cx - cy, cx + cy);
    }
}

// ============ fused pass W+H: real plane -> half spectrum [k_h][k_w] ========
__global__ __launch_bounds__(256) void pass_wh(
    const float* __restrict__ in, float2* __restrict__ out)
{
    __shared__ __align__(16) char ubuf[48 * 27 * sizeof(float2)];  // P / C overlay
    float  (*P)[49] = reinterpret_cast<float  (*)[49]>(ubuf);      // P[w][h]
    float2 (*C)[27] = reinterpret_cast<float2 (*)[27]>(ubuf);      // C[m_h][k_w]
    __shared__ float2 A2[L][L + 2];
    __shared__ float2 B2[LH][L + 1];
    __shared__ float2 TWs[L];

    int t = threadIdx.x;
    int f = blockIdx.x / L, d = blockIdx.x % L;
    const float* src = in + (size_t)f * N3 + (size_t)d * 2304;

    if (t < L) TWs[t] = g_tw1[t];
    for (int idx = t; idx < L * L; idx += 256)
        P[idx % L][idx / L] = src[idx];          // transpose: P[w][h]
    __syncthreads();

    int tx = t & 15, ty = t >> 4;
    int k1 = ty & 7;
    bool g1 = (tx < 10);
    int txg = g1 ? (tx + 16) : 0;

    float2 w8[8];
    {
        int step = (6 * k1) % L, widx = 0;
        #pragma unroll
        for (int n1 = 0; n1 < 8; n1++) { w8[n1] = TWs[widx]; widx += step; if (widx >= L) widx -= L; }
    }

    // ---- stage 1 (w)
    {
        float ar[3][3] = {{0.f}}, ai[3][3] = {{0.f}};
        #pragma unroll
        for (int n1 = 0; n1 < 8; n1++) {
            float2 w = w8[n1];
            #pragma unroll
            for (int a = 0; a < 3; a++) {
                int row = 6 * n1 + ((ty + 16 * a) >> 3);
                #pragma unroll
                for (int b = 0; b < 3; b++) {
                    float p = P[row][tx + 16 * b];
                    ar[a][b] += p * w.x;  ai[a][b] += p * w.y;
                }
            }
        }
        #pragma unroll
        for (int a = 0; a < 3; a++)
            #pragma unroll
            for (int b = 0; b < 3; b++)
                A2[ty + 16 * a][tx + 16 * b] = make_float2(ar[a][b], ai[a][b]);
    }
    __syncthreads();

    // ---- stage 2 (w): k_w = tx+16c (<26), h = ty+16a
    {
        float xr[3][2] = {{0.f}}, xi[3][2] = {{0.f}};
        int r8 = tx & 7;
        int i0 = 0, i1 = 0;
        int k3a = tx, k3b = tx + 16;
        #pragma unroll
        for (int n2 = 0; n2 < 6; n2++) {
            int arow = n2 * 8 + r8;
            float2 w0 = TWs[i0], w1 = TWs[i1];
            i0 += k3a; if (i0 >= L) i0 -= L;
            i1 += k3b; if (i1 >= L) i1 -= L;
            #pragma unroll
            for (int a = 0; a < 3; a++) {
                float2 v = A2[arow][ty + 16 * a];
                xr[a][0] += v.x * w0.x - v.y * w0.y;
                xi[a][0] += v.x * w0.y + v.y * w0.x;
                xr[a][1] += v.x * w1.x - v.y * w1.y;
                xi[a][1] += v.x * w1.y + v.y * w1.x;
            }
        }
        #pragma unroll
        for (int a = 0; a < 3; a++) {
            int h = ty + 16 * a;
            B2[k3a][h] = make_float2(xr[a][0], xi[a][0]);
            if (g1) B2[k3b][h] = make_float2(xr[a][1], xi[a][1]);
        }
    }
    __syncthreads();

    // ---- stage 3 (h): C[m][k_w]
    {
        float cr[3][2] = {{0.f}}, ci[3][2] = {{0.f}};
        #pragma unroll
        for (int n1 = 0; n1 < 8; n1++) {
            float2 w = w8[n1];
            #pragma unroll
            for (int a = 0; a < 3; a++) {
                int row = 6 * n1 + ((ty + 16 * a) >> 3);
                float2 q0 = B2[tx][row];
                float2 q1 = B2[txg][row];
                cr[a][0] += q0.x * w.x - q0.y * w.y;
                ci[a][0] += q0.x * w.y + q0.y * w.x;
                cr[a][1] += q1.x * w.x - q1.y * w.y;
                ci[a][1] += q1.x * w.y + q1.y * w.x;
            }
        }
        __syncthreads();
        #pragma unroll
        for (int a = 0; a < 3; a++) {
            C[ty + 16 * a][tx] = make_float2(cr[a][0], ci[a][0]);
            if (g1) C[ty + 16 * a][tx + 16] = make_float2(cr[a][1], ci[a][1]);
        }
    }
    __syncthreads();

    // ---- stage 4 (h): out[k_h][k_w]
    {
        float xr[3][2] = {{0.f}}, xi[3][2] = {{0.f}};
        int iw[3] = {0, 0, 0};
        #pragma unroll
        for (int n2 = 0; n2 < 6; n2++) {
            int arow = n2 * 8 + k1;
            float2 v0 = C[arow][tx];
            float2 v1 = C[arow][txg];
            #pragma unroll
            for (int a = 0; a < 3; a++) {
                float2 w = TWs[iw[a]];
                iw[a] += ty + 16 * a; if (iw[a] >= L) iw[a] -= L;
                xr[a][0] += v0.x * w.x - v0.y * w.y;
                xi[a][0] += v0.x * w.y + v0.y * w.x;
                xr[a][1] += v1.x * w.x - v1.y * w.y;
                xi[a][1] += v1.x * w.y + v1.y * w.x;
            }
        }
        float2* dst = out + (size_t)(f * L + d) * (L * LH);
        #pragma unroll
        for (int a = 0; a < 3; a++) {
            int k2 = ty + 16 * a;
            dst[(size_t)k2 * LH + tx] = make_float2(xr[a][0], xi[a][0]);
            if (g1) dst[(size_t)k2 * LH + tx + 16] = make_float2(xr[a][1], xi[a][1]);
        }
    }
}

// ============ pass D: complex, DFT along d, fold + Hermitian mirror write ===
__global__ __launch_bounds__(256) void pass_d(
    const float2* __restrict__ in, float* __restrict__ out, float scale)
{
    __shared__ float2 Q2[L][LH + 1];
    __shared__ float2 A2[L][LH + 1];
    __shared__ float2 TWs[L];
    int t = threadIdx.x;
    int f = blockIdx.x / L, k2 = blockIdx.x % L;
    const float2* src = in + ((size_t)f * (L * L) + k2) * LH;

    if (t < L) TWs[t] = g_tw1[t];
    for (int idx = t; idx < L * LH; idx += 256)
        Q2[idx / LH][idx % LH] = src[(size_t)(idx / LH) * (L * LH) + (idx % LH)];
    __syncthreads();

    int tx = t & 15, ty = t >> 4;
    bool g1 = (tx < 10);
    int txg = g1 ? (tx + 16) : 0;

    {
        int k1 = ty & 7;
        float2 w8[8];
        int step = (6 * k1) % L, widx = 0;
        #pragma unroll
        for (int n1 = 0; n1 < 8; n1++) { w8[n1] = TWs[widx]; widx += step; if (widx >= L) widx -= L; }

        float ar[3][2] = {{0.f}}, ai[3][2] = {{0.f}};
        #pragma unroll
        for (int n1 = 0; n1 < 8; n1++) {
            float2 w = w8[n1];
            #pragma unroll
            for (int a = 0; a < 3; a++) {
                int row = 6 * n1 + ((ty + 16 * a) >> 3);
                float2 q0 = Q2[row][tx];
                float2 q1 = Q2[row][txg];
                ar[a][0] += q0.x * w.x - q0.y * w.y;
                ai[a][0] += q0.x * w.y + q0.y * w.x;
                ar[a][1] += q1.x * w.x - q1.y * w.y;
                ai[a][1] += q1.x * w.y + q1.y * w.x;
            }
        }
        __syncthreads();
        #pragma unroll
        for (int a = 0; a < 3; a++) {
            A2[ty + 16 * a][tx] = make_float2(ar[a][0], ai[a][0]);
            if (g1) A2[ty + 16 * a][tx + 16] = make_float2(ar[a][1], ai[a][1]);
        }
    }
    __syncthreads();

    {
        int r8 = ty & 7;
        float xr[3][2] = {{0.f}}, xi[3][2] = {{0.f}};
        int iw[3] = {0, 0, 0};
        #pragma unroll
        for (int n2 = 0; n2 < 6; n2++) {
            int arow = n2 * 8 + r8;
            float2 v0 = A2[arow][tx];
            float2 v1 = A2[arow][txg];
            #pragma unroll
            for (int a = 0; a < 3; a++) {
                float2 w = TWs[iw[a]];
                iw[a] += ty + 16 * a; if (iw[a] >= L) iw[a] -= L;
                xr[a][0] += v0.x * w.x - v0.y * w.y;
                xi[a][0] += v0.x * w.y + v0.y * w.x;
                xr[a][1] += v1.x * w.x - v1.y * w.y;
                xi[a][1] += v1.x * w.y + v1.y * w.x;
            }
        }
        int mk2 = (k2 == 0) ? 0 : L - k2;
        float* dstD = out + (size_t)f * N3 + (size_t)k2 * L;
        float* dstM = out + (size_t)f * N3 + (size_t)mk2 * L;
        int k3a = tx, k3b = tx + 16;
        int m3a = (k3a == 0) ? 0 : L - k3a;
        int m3b = L - k3b;
        #pragma unroll
        for (int a = 0; a < 3; a++) {
            int k1 = ty + 16 * a;
            int mk1 = (k1 == 0) ? 0 : L - k1;
            dstD[(size_t)k1 * 2304 + k3a]  = scale * (xr[a][0] - xi[a][0]);
            dstM[(size_t)mk1 * 2304 + m3a] = scale * (xr[a][0] + xi[a][0]);
            if (g1) {
                dstD[(size_t)k1 * 2304 + k3b]  = scale * (xr[a][1] - xi[a][1]);
                dstM[(size_t)mk1 * 2304 + m3b] = scale * (xr[a][1] + xi[a][1]);
            }
        }
    }
}

// ---------------- Y path -----------------------------------------------------
__global__ void ykernel1(const float* __restrict__ w) {
    int idx = blockIdx.x * blockDim.x + threadIdx.x;
    if (idx >= CF * 12 * 12 * L) return;
    int k3 = idx % L;
    int r  = idx / L;
    const float* wp = w + r * 12;
    float ar = 0.f, ai = 0.f;
    #pragma unroll
    for (int n3 = 0; n3 < 12; n3++) {
        float2 e = g_tw[k3 * L + n3];
        float  v = wp[n3];
        ar += v * e.x;  ai += v * e.y;
    }
    g_T1[idx] = make_float2(ar, ai);
}

// fused ykernel2 + ykernel3: per (io, quarter of k2).
// T1[io] (12x12x48 complex) staged in dynamic smem; per k2: T2col in smem,
// then fold -> g_Yh. Eliminates the g_T2 DRAM round trip.
__global__ __launch_bounds__(256) void ykernel23() {
    extern __shared__ float2 ysm[];
    float2* T1s = ysm;                      // [n1*576 + n2*48 + k3], 6912 float2
    float2* T2c = ysm + 6912;               // [n1*49 + k3], 588 float2
    __shared__ float2 TWs[L];
    __shared__ float2 EMPs[L];

    int t  = threadIdx.x;
    int io = blockIdx.x >> 2;
    int kt = blockIdx.x & 3;

    if (t < L) { TWs[t] = g_tw1[t]; EMPs[t] = g_emp[t]; }
    const float2* src = g_T1 + (size_t)io * 6912;
    for (int idx = t; idx < 6912; idx += 256) T1s[idx] = src[idx];
    __syncthreads();

    int tx = t & 15, ty = t >> 4;

    for (int kk = 0; kk < 12; kk++) {
        int k2 = kt * 12 + kk;

        // T2col[n1][k3] = sum_{n2<12} T1s[n1][n2][k3] * W48^{k2*n2}
        for (int idx = t; idx < 576; idx += 256) {
            int n1 = idx / 48, k3 = idx - n1 * 48;
            const float2* tp = T1s + n1 * 576 + k3;
            float ar = 0.f, ai = 0.f;
            int iw = 0;
            #pragma unroll
            for (int n2 = 0; n2 < 12; n2++) {
                float2 v = tp[n2 * 48];
                float2 e = TWs[iw];
                iw += k2; if (iw >= L) iw -= L;
                ar += v.x * e.x - v.y * e.y;
                ai += v.x * e.y + v.y * e.x;
            }
            T2c[n1 * 49 + k3] = make_float2(ar, ai);
        }
        __syncthreads();

        // fold: Yh[io,k1,k2,k3] = sum_{n1} Re(T2c)*(c-s) - Im(T2c)*(c+s)
        {
            float acc[3][3] = {{0.f}};
            int iw2[3] = {0, 0, 0};
            #pragma unroll
            for (int n1 = 0; n1 < 12; n1++) {
                float2 tv[3];
                #pragma unroll
                for (int b = 0; b < 3; b++) tv[b] = T2c[n1 * 49 + tx + 16 * b];
                #pragma unroll
                for (int a = 0; a < 3; a++) {
                    float2 e = EMPs[iw2[a]];
                    iw2[a] += ty + 16 * a; if (iw2[a] >= L) iw2[a] -= L;
                    #pragma unroll
                    for (int b = 0; b < 3; b++)
                        acc[a][b] += tv[b].x * e.x - tv[b].y * e.y;
                }
            }
            #pragma unroll
            for (int a = 0; a < 3; a++)
                #pragma unroll
                for (int b = 0; b < 3; b++)
                    g_Yh[(size_t)io * N3 + (size_t)(ty + 16 * a) * 2304
                         + (size_t)k2 * 48 + tx + 16 * b] = acc[a][b];
        }
        __syncthreads();
    }
}

// ---------------- coalesced paired mix ---------------------------------------
#define MK    16
#define MPIT  20
__global__ __launch_bounds__(256) void mix3() {
    extern __shared__ float sm[];
    float* Xa = sm;
    float* Xb = Xa + 128 * MPIT;
    float* Ya = Xb + 128 * MPIT;
    float* Yb = Ya + 256 * MPIT;

    int t  = threadIdx.x;
    int k0 = blockIdx.x * MK;

    for (int q = t; q < 128 * MK; q += 256) {
        int kk = q & 15, bi = q >> 4;
        int k = k0 + kk; if (k > NHALF) k = NHALF;
        int sk = (k == 0) ? 0 : (N3 - k);
        Xa[bi * MPIT + kk] = g_Xh[(size_t)bi * N3 + k];
        Xb[bi * MPIT + kk] = g_Xh[(size_t)bi * N3 + sk];
    }
    for (int q = t; q < 256 * MK; q += 256) {
        int kk = q & 15, io = q >> 4;
        int k = k0 + kk; if (k > NHALF) k = NHALF;
        int sk = (k == 0) ? 0 : (N3 - k);
        Ya[io * MPIT + kk] = g_Yh[(size_t)io * N3 + k];
        Yb[io * MPIT + kk] = g_Yh[(size_t)io * N3 + sk];
    }
    __syncthreads();

    int kh = t >> 7;
    int b  = (t >> 4) & 7;
    int o  = t & 15;

    float acc[8] = {0,0,0,0,0,0,0,0}, accs[8] = {0,0,0,0,0,0,0,0};
    #pragma unroll 4
    for (int i = 0; i < 16; i++) {
        const float* xa = Xa + (b * 16 + i) * MPIT + kh * 8;
        const float* xb = Xb + (b * 16 + i) * MPIT + kh * 8;
        const float* ya = Ya + (i * 16 + o) * MPIT + kh * 8;
        const float* yb = Yb + (i * 16 + o) * MPIT + kh * 8;
        float xk[8], xs[8], yk[8], ys[8];
        *(float4*)&xk[0] = *(const float4*)xa;  *(float4*)&xk[4] = *(const float4*)(xa + 4);
        *(float4*)&xs[0] = *(const float4*)xb;  *(float4*)&xs[4] = *(const float4*)(xb + 4);
        *(float4*)&yk[0] = *(const float4*)ya;  *(float4*)&yk[4] = *(const float4*)(ya + 4);
        *(float4*)&ys[0] = *(const float4*)yb;  *(float4*)&ys[4] = *(const float4*)(yb + 4);
        #pragma unroll
        for (int kk = 0; kk < 8; kk++) {
            float xe = 0.5f * (xk[kk] + xs[kk]);
            float xo = 0.5f * (xk[kk] - xs[kk]);
            acc[kk]  += xe * yk[kk] + xo * ys[kk];
            accs[kk] += xe * ys[kk] - xo * yk[kk];
        }
    }

    int kb = k0 + kh * 8;
    float* zrow = g_Z + (size_t)(b * 16 + o) * N3;
    if (kb + 7 <= NHALF) {
        *(float4*)(zrow + kb)     = make_float4(acc[0], acc[1], acc[2], acc[3]);
        *(float4*)(zrow + kb + 4) = make_float4(acc[4], acc[5], acc[6], acc[7]);
    } else {
        #pragma unroll
        for (int kk = 0; kk < 8; kk++)
            if (kb + kk <= NHALF) zrow[kb + kk] = acc[kk];
    }
    #pragma unroll
    for (int kk = 0; kk < 8; kk++) {
        int k = kb + kk;
        if (k >= 1 && k <= NHALF - 1) zrow[N3 - k] = accs[kk];
    }
}

// ---------------- launcher ----------------------------------------------------
extern "C" void kernel_launch(void* const* d_in, const int* in_sizes, int n_in,
                              void* d_out, int out_size) {
    (void)in_sizes; (void)n_in; (void)out_size;
    static float2* bufB = nullptr;
    static float*  xh   = nullptr;
    static float*  z    = nullptr;
    if (!bufB) {
        cudaGetSymbolAddress((void**)&bufB, g_bufB);
        cudaGetSymbolAddress((void**)&xh,   g_Xh);
        cudaGetSymbolAddress((void**)&z,    g_Z);
        cudaFuncSetAttribute(mix3, cudaFuncAttributeMaxDynamicSharedMemorySize,
                             (128 * MPIT * 2 + 256 * MPIT * 2) * (int)sizeof(float));
        cudaFuncSetAttribute(ykernel23, cudaFuncAttributeMaxDynamicSharedMemorySize,
                             (6912 + 12 * 49) * (int)sizeof(float2));
    }
    const float* x  = (const float*)d_in[0];   // [8,16,48,48,48]
    const float* wt = (const float*)d_in[2];   // [16,16,12,12,12]
    float* out = (float*)d_out;

    const int mix_smem = (128 * MPIT * 2 + 256 * MPIT * 2) * (int)sizeof(float);
    const int mix_grid = NHALF / MK + 1;
    const int y_smem   = (6912 + 12 * 49) * (int)sizeof(float2);   // ~60 KB

    init_tw<<<(L * L + 255) / 256, 256>>>();

    ykernel1<<<(CF * 12 * 12 * L + 255) / 256, 256>>>(wt);
    ykernel23<<<CF * 4, 256, y_smem>>>();

    // forward: x -> Xh
    pass_wh<<<BF * L, 256>>>(x, bufB);
    pass_d <<<BF * L, 256>>>(bufB, xh, 1.f);

    mix3<<<mix_grid, 256, mix_smem>>>();

    // inverse: Z -> out (scaled 1/N3)
    pass_wh<<<BF * L, 256>>>(z, bufB);
    pass_d <<<BF * L, 256>>>(bufB, out, 1.f / (float)N3);
}

// round 8
// speedup vs baseline: 1.1454x; 1.0368x over previous
#include <cuda_runtime.h>
#include <math.h>

#define L    48
#define LH   26                 // kept frequencies (Hermitian half: 0..25)
#define N3   110592             // 48^3
#define NHALF 55296             // N3/2
#define BF   128                // B*CIN  fields for x / Z
#define CF   256                // CIN*COUT fields for Y
#define PLH  59904              // 48*48*26

// ---------------- scratch (static device memory) ---------------------------
__device__ float2 g_tw[L * L];
__device__ float2 g_tw1[L];
__device__ float2 g_emp[L];
__device__ float2 g_bufB[BF * PLH];            // 61 MB intermediate
__device__ float  g_Xh[BF * N3];
__device__ float  g_Yh[CF * N3];
__device__ float  g_Z [BF * N3];
__device__ float2 g_T1[CF * 12 * 12 * L];

// ---------------- twiddle init ---------------------------------------------
__global__ void init_tw() {
    int idx = blockIdx.x * blockDim.x + threadIdx.x;
    if (idx < L * L) {
        int k = idx / L, n = idx % L;
        int m = (k * n) % L;
        double a = -6.283185307179586476925286766559 * (double)m / (double)L;
        g_tw[idx] = make_float2((float)cos(a), (float)sin(a));
    }
    if (idx < L) {
        double a = -6.283185307179586476925286766559 * (double)idx / (double)L;
        float cx = (float)cos(a), cy = (float)sin(a);
        g_tw1[idx] = make_float2(cx, cy);
        g_emp[idx] = make_float2(cx - cy, cx + cy);
    }
}

// ============ fused pass W+H: real plane -> half spectrum [k_h][k_w] ========
// smem reduced to ~30KB: B2 overlays dead A2; regs capped for 5 blocks/SM.
__global__ __launch_bounds__(256, 5) void pass_wh(
    const float* __restrict__ in, float2* __restrict__ out)
{
    __shared__ __align__(16) char ubuf[48 * 27 * sizeof(float2)];  // P / C overlay
    float  (*P)[49] = reinterpret_cast<float  (*)[49]>(ubuf);      // P[w][h]
    float2 (*C)[27] = reinterpret_cast<float2 (*)[27]>(ubuf);      // C[m_h][k_w]
    __shared__ float2 A2[L][L + 2];                                // 19200 B
    float2 (*B2)[49] = reinterpret_cast<float2 (*)[49]>(&A2[0][0]); // overlay (needs 1274 < 2400 float2)
    __shared__ float2 TWs[L];

    int t = threadIdx.x;
    int f = blockIdx.x / L, d = blockIdx.x % L;
    const float* src = in + (size_t)f * N3 + (size_t)d * 2304;

    if (t < L) TWs[t] = g_tw1[t];
    for (int idx = t; idx < L * L; idx += 256)
        P[idx % L][idx / L] = src[idx];          // transpose: P[w][h]
    __syncthreads();

    int tx = t & 15, ty = t >> 4;
    int k1 = ty & 7;
    bool g1 = (tx < 10);
    int txg = g1 ? (tx + 16) : 0;

    float2 w8[8];
    {
        int step = (6 * k1) % L, widx = 0;
        #pragma unroll
        for (int n1 = 0; n1 < 8; n1++) { w8[n1] = TWs[widx]; widx += step; if (widx >= L) widx -= L; }
    }

    // ---- stage 1 (w): A[m][h]
    {
        float ar[3][3] = {{0.f}}, ai[3][3] = {{0.f}};
        #pragma unroll
        for (int n1 = 0; n1 < 8; n1++) {
            float2 w = w8[n1];
            #pragma unroll
            for (int a = 0; a < 3; a++) {
                int row = 6 * n1 + ((ty + 16 * a) >> 3);
                #pragma unroll
                for (int b = 0; b < 3; b++) {
                    float p = P[row][tx + 16 * b];
                    ar[a][b] += p * w.x;  ai[a][b] += p * w.y;
                }
            }
        }
        #pragma unroll
        for (int a = 0; a < 3; a++)
            #pragma unroll
            for (int b = 0; b < 3; b++)
                A2[ty + 16 * a][tx + 16 * b] = make_float2(ar[a][b], ai[a][b]);
    }
    __syncthreads();

    // ---- stage 2 (w): k_w = tx+16c (<26), h = ty+16a
    {
        float xr[3][2] = {{0.f}}, xi[3][2] = {{0.f}};
        int r8 = tx & 7;
        int i0 = 0, i1 = 0;
        int k3a = tx, k3b = tx + 16;
        #pragma unroll
        for (int n2 = 0; n2 < 6; n2++) {
            int arow = n2 * 8 + r8;
            float2 w0 = TWs[i0], w1 = TWs[i1];
            i0 += k3a; if (i0 >= L) i0 -= L;
            i1 += k3b; if (i1 >= L) i1 -= L;
            #pragma unroll
            for (int a = 0; a < 3; a++) {
                float2 v = A2[arow][ty + 16 * a];
                xr[a][0] += v.x * w0.x - v.y * w0.y;
                xi[a][0] += v.x * w0.y + v.y * w0.x;
                xr[a][1] += v.x * w1.x - v.y * w1.y;
                xi[a][1] += v.x * w1.y + v.y * w1.x;
            }
        }
        __syncthreads();                         // A2 reads complete; B2 overlays it
        #pragma unroll
        for (int a = 0; a < 3; a++) {
            int h = ty + 16 * a;
            B2[k3a][h] = make_float2(xr[a][0], xi[a][0]);
            if (g1) B2[k3b][h] = make_float2(xr[a][1], xi[a][1]);
        }
    }
    __syncthreads();

    // ---- stage 3 (h): C[m][k_w]
    {
        float cr[3][2] = {{0.f}}, ci[3][2] = {{0.f}};
        #pragma unroll
        for (int n1 = 0; n1 < 8; n1++) {
            float2 w = w8[n1];
            #pragma unroll
            for (int a = 0; a < 3; a++) {
                int row = 6 * n1 + ((ty + 16 * a) >> 3);
                float2 q0 = B2[tx][row];
                float2 q1 = B2[txg][row];
                cr[a][0] += q0.x * w.x - q0.y * w.y;
                ci[a][0] += q0.x * w.y + q0.y * w.x;
                cr[a][1] += q1.x * w.x - q1.y * w.y;
                ci[a][1] += q1.x * w.y + q1.y * w.x;
            }
        }
        __syncthreads();                         // P region dead; C overlays ubuf
        #pragma unroll
        for (int a = 0; a < 3; a++) {
            C[ty + 16 * a][tx] = make_float2(cr[a][0], ci[a][0]);
            if (g1) C[ty + 16 * a][tx + 16] = make_float2(cr[a][1], ci[a][1]);
        }
    }
    __syncthreads();

    // ---- stage 4 (h): out[k_h][k_w]
    {
        float xr[3][2] = {{0.f}}, xi[3][2] = {{0.f}};
        int iw[3] = {0, 0, 0};
        #pragma unroll
        for (int n2 = 0; n2 < 6; n2++) {
            int arow = n2 * 8 + k1;
            float2 v0 = C[arow][tx];
            float2 v1 = C[arow][txg];
            #pragma unroll
            for (int a = 0; a < 3; a++) {
                float2 w = TWs[iw[a]];
                iw[a] += ty + 16 * a; if (iw[a] >= L) iw[a] -= L;
                xr[a][0] += v0.x * w.x - v0.y * w.y;
                xi[a][0] += v0.x * w.y + v0.y * w.x;
                xr[a][1] += v1.x * w.x - v1.y * w.y;
                xi[a][1] += v1.x * w.y + v1.y * w.x;
            }
        }
        float2* dst = out + (size_t)(f * L + d) * (L * LH);
        #pragma unroll
        for (int a = 0; a < 3; a++) {
            int k2 = ty + 16 * a;
            dst[(size_t)k2 * LH + tx] = make_float2(xr[a][0], xi[a][0]);
            if (g1) dst[(size_t)k2 * LH + tx + 16] = make_float2(xr[a][1], xi[a][1]);
        }
    }
}

// ============ pass D: complex, DFT along d, fold + Hermitian mirror write ===
__global__ __launch_bounds__(256, 5) void pass_d(
    const float2* __restrict__ in, float* __restrict__ out, float scale)
{
    __shared__ float2 Q2[L][LH + 1];
    __shared__ float2 A2[L][LH + 1];
    __shared__ float2 TWs[L];
    int t = threadIdx.x;
    int f = blockIdx.x / L, k2 = blockIdx.x % L;
    const float2* src = in + ((size_t)f * (L * L) + k2) * LH;

    if (t < L) TWs[t] = g_tw1[t];
    for (int idx = t; idx < L * LH; idx += 256)
        Q2[idx / LH][idx % LH] = src[(size_t)(idx / LH) * (L * LH) + (idx % LH)];
    __syncthreads();

    int tx = t & 15, ty = t >> 4;
    bool g1 = (tx < 10);
    int txg = g1 ? (tx + 16) : 0;

    {
        int k1 = ty & 7;
        float2 w8[8];
        int step = (6 * k1) % L, widx = 0;
        #pragma unroll
        for (int n1 = 0; n1 < 8; n1++) { w8[n1] = TWs[widx]; widx += step; if (widx >= L) widx -= L; }

        float ar[3][2] = {{0.f}}, ai[3][2] = {{0.f}};
        #pragma unroll
        for (int n1 = 0; n1 < 8; n1++) {
            float2 w = w8[n1];
            #pragma unroll
            for (int a = 0; a < 3; a++) {
                int row = 6 * n1 + ((ty + 16 * a) >> 3);
                float2 q0 = Q2[row][tx];
                float2 q1 = Q2[row][txg];
                ar[a][0] += q0.x * w.x - q0.y * w.y;
                ai[a][0] += q0.x * w.y + q0.y * w.x;
                ar[a][1] += q1.x * w.x - q1.y * w.y;
                ai[a][1] += q1.x * w.y + q1.y * w.x;
            }
        }
        __syncthreads();
        #pragma unroll
        for (int a = 0; a < 3; a++) {
            A2[ty + 16 * a][tx] = make_float2(ar[a][0], ai[a][0]);
            if (g1) A2[ty + 16 * a][tx + 16] = make_float2(ar[a][1], ai[a][1]);
        }
    }
    __syncthreads();

    {
        int r8 = ty & 7;
        float xr[3][2] = {{0.f}}, xi[3][2] = {{0.f}};
        int iw[3] = {0, 0, 0};
        #pragma unroll
        for (int n2 = 0; n2 < 6; n2++) {
            int arow = n2 * 8 + r8;
            float2 v0 = A2[arow][tx];
            float2 v1 = A2[arow][txg];
            #pragma unroll
            for (int a = 0; a < 3; a++) {
                float2 w = TWs[iw[a]];
                iw[a] += ty + 16 * a; if (iw[a] >= L) iw[a] -= L;
                xr[a][0] += v0.x * w.x - v0.y * w.y;
                xi[a][0] += v0.x * w.y + v0.y * w.x;
                xr[a][1] += v1.x * w.x - v1.y * w.y;
                xi[a][1] += v1.x * w.y + v1.y * w.x;
            }
        }
        int mk2 = (k2 == 0) ? 0 : L - k2;
        float* dstD = out + (size_t)f * N3 + (size_t)k2 * L;
        float* dstM = out + (size_t)f * N3 + (size_t)mk2 * L;
        int k3a = tx, k3b = tx + 16;
        int m3a = (k3a == 0) ? 0 : L - k3a;
        int m3b = L - k3b;
        #pragma unroll
        for (int a = 0; a < 3; a++) {
            int k1 = ty + 16 * a;
            int mk1 = (k1 == 0) ? 0 : L - k1;
            dstD[(size_t)k1 * 2304 + k3a]  = scale * (xr[a][0] - xi[a][0]);
            dstM[(size_t)mk1 * 2304 + m3a] = scale * (xr[a][0] + xi[a][0]);
            if (g1) {
                dstD[(size_t)k1 * 2304 + k3b]  = scale * (xr[a][1] - xi[a][1]);
                dstM[(size_t)mk1 * 2304 + m3b] = scale * (xr[a][1] + xi[a][1]);
            }
        }
    }
}

// ---------------- Y path -----------------------------------------------------
__global__ void ykernel1(const float* __restrict__ w) {
    int idx = blockIdx.x * blockDim.x + threadIdx.x;
    if (idx >= CF * 12 * 12 * L) return;
    int k3 = idx % L;
    int r  = idx / L;
    const float* wp = w + r * 12;
    float ar = 0.f, ai = 0.f;
    #pragma unroll
    for (int n3 = 0; n3 < 12; n3++) {
        float2 e = g_tw[k3 * L + n3];
        float  v = wp[n3];
        ar += v * e.x;  ai += v * e.y;
    }
    g_T1[idx] = make_float2(ar, ai);
}

// fused ykernel2 + ykernel3 (per io, quarter of k2); T1 slice in dynamic smem.
__global__ __launch_bounds__(256) void ykernel23() {
    extern __shared__ float2 ysm[];
    float2* T1s = ysm;                      // 6912 float2
    float2* T2c = ysm + 6912;               // [n1*49 + k3]
    __shared__ float2 TWs[L];
    __shared__ float2 EMPs[L];

    int t  = threadIdx.x;
    int io = blockIdx.x >> 2;
    int kt = blockIdx.x & 3;

    if (t < L) { TWs[t] = g_tw1[t]; EMPs[t] = g_emp[t]; }
    const float2* src = g_T1 + (size_t)io * 6912;
    for (int idx = t; idx < 6912; idx += 256) T1s[idx] = src[idx];
    __syncthreads();

    int tx = t & 15, ty = t >> 4;

    for (int kk = 0; kk < 12; kk++) {
        int k2 = kt * 12 + kk;

        for (int idx = t; idx < 576; idx += 256) {
            int n1 = idx / 48, k3 = idx - n1 * 48;
            const float2* tp = T1s + n1 * 576 + k3;
            float ar = 0.f, ai = 0.f;
            int iw = 0;
            #pragma unroll
            for (int n2 = 0; n2 < 12; n2++) {
                float2 v = tp[n2 * 48];
                float2 e = TWs[iw];
                iw += k2; if (iw >= L) iw -= L;
                ar += v.x * e.x - v.y * e.y;
                ai += v.x * e.y + v.y * e.x;
            }
            T2c[n1 * 49 + k3] = make_float2(ar, ai);
        }
        __syncthreads();

        {
            float acc[3][3] = {{0.f}};
            int iw2[3] = {0, 0, 0};
            #pragma unroll
            for (int n1 = 0; n1 < 12; n1++) {
                float2 tv[3];
                #pragma unroll
                for (int b = 0; b < 3; b++) tv[b] = T2c[n1 * 49 + tx + 16 * b];
                #pragma unroll
                for (int a = 0; a < 3; a++) {
                    float2 e = EMPs[iw2[a]];
                    iw2[a] += ty + 16 * a; if (iw2[a] >= L) iw2[a] -= L;
                    #pragma unroll
                    for (int b = 0; b < 3; b++)
                        acc[a][b] += tv[b].x * e.x - tv[b].y * e.y;
                }
            }
            #pragma unroll
            for (int a = 0; a < 3; a++)
                #pragma unroll
                for (int b = 0; b < 3; b++)
                    g_Yh[(size_t)io * N3 + (size_t)(ty + 16 * a) * 2304
                         + (size_t)k2 * 48 + tx + 16 * b] = acc[a][b];
        }
        __syncthreads();
    }
}

// ---------------- coalesced paired mix (MK=8, 36KB smem) ---------------------
#define MK    8
#define MPIT  12
__global__ __launch_bounds__(256) void mix3() {
    extern __shared__ float sm[];
    float* Xa = sm;                        // [128][MPIT]
    float* Xb = Xa + 128 * MPIT;
    float* Ya = Xb + 128 * MPIT;           // [256][MPIT]
    float* Yb = Ya + 256 * MPIT;

    int t  = threadIdx.x;
    int k0 = blockIdx.x * MK;

    for (int q = t; q < 128 * MK; q += 256) {
        int kk = q & 7, bi = q >> 3;
        int k = k0 + kk; if (k > NHALF) k = NHALF;
        int sk = (k == 0) ? 0 : (N3 - k);
        Xa[bi * MPIT + kk] = g_Xh[(size_t)bi * N3 + k];
        Xb[bi * MPIT + kk] = g_Xh[(size_t)bi * N3 + sk];
    }
    for (int q = t; q < 256 * MK; q += 256) {
        int kk = q & 7, io = q >> 3;
        int k = k0 + kk; if (k > NHALF) k = NHALF;
        int sk = (k == 0) ? 0 : (N3 - k);
        Ya[io * MPIT + kk] = g_Yh[(size_t)io * N3 + k];
        Yb[io * MPIT + kk] = g_Yh[(size_t)io * N3 + sk];
    }
    __syncthreads();

    int kh = t >> 7;                       // 0/1: k offset kh*4
    int b  = (t >> 4) & 7;
    int o  = t & 15;

    float acc[4] = {0,0,0,0}, accs[4] = {0,0,0,0};
    #pragma unroll 4
    for (int i = 0; i < 16; i++) {
        const float* xa = Xa + (b * 16 + i) * MPIT + kh * 4;
        const float* xb = Xb + (b * 16 + i) * MPIT + kh * 4;
        const float* ya = Ya + (i * 16 + o) * MPIT + kh * 4;
        const float* yb = Yb + (i * 16 + o) * MPIT + kh * 4;
        float xk[4], xs[4], yk[4], ys[4];
        *(float4*)&xk[0] = *(const float4*)xa;
        *(float4*)&xs[0] = *(const float4*)xb;
        *(float4*)&yk[0] = *(const float4*)ya;
        *(float4*)&ys[0] = *(const float4*)yb;
        #pragma unroll
        for (int kk = 0; kk < 4; kk++) {
            float xe = 0.5f * (xk[kk] + xs[kk]);
            float xo = 0.5f * (xk[kk] - xs[kk]);
            acc[kk]  += xe * yk[kk] + xo * ys[kk];
            accs[kk] += xe * ys[kk] - xo * yk[kk];
        }
    }

    int kb = k0 + kh * 4;
    float* zrow = g_Z + (size_t)(b * 16 + o) * N3;
    if (kb + 3 <= NHALF) {
        *(float4*)(zrow + kb) = make_float4(acc[0], acc[1], acc[2], acc[3]);
    } else {
        #pragma unroll
        for (int kk = 0; kk < 4; kk++)
            if (kb + kk <= NHALF) zrow[kb + kk] = acc[kk];
    }
    #pragma unroll
    for (int kk = 0; kk < 4; kk++) {
        int k = kb + kk;
        if (k >= 1 && k <= NHALF - 1) zrow[N3 - k] = accs[kk];
    }
}

// ---------------- launcher ----------------------------------------------------
extern "C" void kernel_launch(void* const* d_in, const int* in_sizes, int n_in,
                              void* d_out, int out_size) {
    (void)in_sizes; (void)n_in; (void)out_size;
    static float2* bufB = nullptr;
    static float*  xh   = nullptr;
    static float*  z    = nullptr;
    if (!bufB) {
        cudaGetSymbolAddress((void**)&bufB, g_bufB);
        cudaGetSymbolAddress((void**)&xh,   g_Xh);
        cudaGetSymbolAddress((void**)&z,    g_Z);
        cudaFuncSetAttribute(mix3, cudaFuncAttributeMaxDynamicSharedMemorySize,
                             (128 * MPIT * 2 + 256 * MPIT * 2) * (int)sizeof(float));
        cudaFuncSetAttribute(ykernel23, cudaFuncAttributeMaxDynamicSharedMemorySize,
                             (6912 + 12 * 49) * (int)sizeof(float2));
    }
    const float* x  = (const float*)d_in[0];   // [8,16,48,48,48]
    const float* wt = (const float*)d_in[2];   // [16,16,12,12,12]
    float* out = (float*)d_out;

    const int mix_smem = (128 * MPIT * 2 + 256 * MPIT * 2) * (int)sizeof(float);
    const int mix_grid = NHALF / MK + 1;
    const int y_smem   = (6912 + 12 * 49) * (int)sizeof(float2);

    init_tw<<<(L * L + 255) / 256, 256>>>();

    ykernel1<<<(CF * 12 * 12 * L + 255) / 256, 256>>>(wt);
    ykernel23<<<CF * 4, 256, y_smem>>>();

    // forward: x -> Xh
    pass_wh<<<BF * L, 256>>>(x, bufB);
    pass_d <<<BF * L, 256>>>(bufB, xh, 1.f);

    mix3<<<mix_grid, 256, mix_smem>>>();

    // inverse: Z -> out (scaled 1/N3)
    pass_wh<<<BF * L, 256>>>(z, bufB);
    pass_d <<<BF * L, 256>>>(bufB, out, 1.f / (float)N3);
}

// round 10
// speedup vs baseline: 1.2449x; 1.0869x over previous
#include <cuda_runtime.h>
#include <math.h>

#define L    48
#define LH   26                 // kept frequencies (Hermitian half: 0..25)
#define N3   110592             // 48^3
#define NHALF 55296             // N3/2
#define BF   128                // B*CIN  fields for x / Z
#define CF   256                // CIN*COUT fields for Y
#define PLH  59904              // 48*48*26

// ---------------- scratch (static device memory) ---------------------------
__device__ float2 g_tw[L * L];
__device__ float2 g_tw1[L];
__device__ float2 g_emp[L];
__device__ float2 g_bufB[BF * PLH];            // 61 MB intermediate
__device__ float  g_Xh[BF * N3];
__device__ float  g_Yh[CF * N3];
__device__ float  g_Z [BF * N3];
__device__ float2 g_T1[CF * 12 * 12 * L];

// ---------------- twiddle init ---------------------------------------------
__global__ void init_tw() {
    int idx = blockIdx.x * blockDim.x + threadIdx.x;
    if (idx < L * L) {
        int k = idx / L, n = idx % L;
        int m = (k * n) % L;
        double a = -6.283185307179586476925286766559 * (double)m / (double)L;
        g_tw[idx] = make_float2((float)cos(a), (float)sin(a));
    }
    if (idx < L) {
        double a = -6.283185307179586476925286766559 * (double)idx / (double)L;
        float cx = (float)cos(a), cy = (float)sin(a);
        g_tw1[idx] = make_float2(cx, cy);
        g_emp[idx] = make_float2(cx - cy, cx + cy);
    }
}

// ============ fused pass W+H: real plane -> half spectrum [k_h][k_w] ========
// Radix-8 stages use outer-product blocking: thread = (n2, j), all 8 k1 in
// registers, W8 roots in registers -> each smem element loaded once.
// ALL __syncthreads() at uniform program points (no divergent barriers).
__global__ __launch_bounds__(256, 5) void pass_wh(
    const float* __restrict__ in, float2* __restrict__ out)
{
    __shared__ __align__(16) char ubuf[48 * 27 * sizeof(float2)];  // P / C overlay
    float  (*P)[50] = reinterpret_cast<float  (*)[50]>(ubuf);      // P[w][h] 9600B
    float2 (*C)[27] = reinterpret_cast<float2 (*)[27]>(ubuf);      // C[m_h][k_w]
    __shared__ float2 A2[L][L + 1];                                // 18816 B
    float2 (*B2)[49] = reinterpret_cast<float2 (*)[49]>(&A2[0][0]); // overlay (1274 < 2352 f2)
    __shared__ float2 TWs[L];

    int t = threadIdx.x;
    int f = blockIdx.x / L, d = blockIdx.x % L;
    const float* src = in + (size_t)f * N3 + (size_t)d * 2304;

    if (t < L) TWs[t] = g_tw1[t];
    for (int idx = t; idx < L * L; idx += 256)
        P[idx % L][idx / L] = src[idx];          // transpose: P[w][h]
    __syncthreads();

    float2 W8[8];
    #pragma unroll
    for (int u = 0; u < 8; u++) W8[u] = TWs[6 * u];

    int tx = t & 15, ty = t >> 4;
    int k1r = ty & 7;
    bool g1 = (tx < 10);
    int txg = g1 ? (tx + 16) : 0;

    // ---- stage 1 (w, real radix-8): A[n2*8+k1][j] for all k1 ---------------
    for (int u = t; u < 6 * 48; u += 256) {
        int n2 = u / 48, j = u - n2 * 48;
        float ar[8] = {0,0,0,0,0,0,0,0}, ai[8] = {0,0,0,0,0,0,0,0};
        #pragma unroll
        for (int n1 = 0; n1 < 8; n1++) {
            float p = P[6 * n1 + n2][j];
            #pragma unroll
            for (int k1 = 0; k1 < 8; k1++) {
                float2 w = W8[(n1 * k1) & 7];
                ar[k1] += p * w.x;  ai[k1] += p * w.y;
            }
        }
        #pragma unroll
        for (int k1 = 0; k1 < 8; k1++)
            A2[n2 * 8 + k1][j] = make_float2(ar[k1], ai[k1]);
    }
    __syncthreads();

    // ---- stage 2 (w, radix-6): k_w = tx+16c (<26), h = ty+16a ---------------
    {
        float xr[3][2] = {{0.f}}, xi[3][2] = {{0.f}};
        int r8 = tx & 7;
        int i0 = 0, i1 = 0;
        int k3a = tx, k3b = tx + 16;
        #pragma unroll
        for (int n2 = 0; n2 < 6; n2++) {
            int arow = n2 * 8 + r8;
            float2 w0 = TWs[i0], w1 = TWs[i1];
            i0 += k3a; if (i0 >= L) i0 -= L;
            i1 += k3b; if (i1 >= L) i1 -= L;
            #pragma unroll
            for (int a = 0; a < 3; a++) {
                float2 v = A2[arow][ty + 16 * a];
                xr[a][0] += v.x * w0.x - v.y * w0.y;
                xi[a][0] += v.x * w0.y + v.y * w0.x;
                xr[a][1] += v.x * w1.x - v.y * w1.y;
                xi[a][1] += v.x * w1.y + v.y * w1.x;
            }
        }
        __syncthreads();                         // A2 reads complete; B2 overlays it
        #pragma unroll
        for (int a = 0; a < 3; a++) {
            int h = ty + 16 * a;
            B2[k3a][h] = make_float2(xr[a][0], xi[a][0]);
            if (g1) B2[k3b][h] = make_float2(xr[a][1], xi[a][1]);
        }
    }
    __syncthreads();

    // ---- stage 3 (h, complex radix-8): C[n2*8+k1][k_w], thread = (n2,k_w) ---
    {
        bool act = (t < 6 * 26);
        int n2 = 0, kw = 0;
        float cr[8] = {0,0,0,0,0,0,0,0}, ci[8] = {0,0,0,0,0,0,0,0};
        if (act) {
            n2 = t / 26;  kw = t - n2 * 26;
            #pragma unroll
            for (int n1 = 0; n1 < 8; n1++) {
                float2 q = B2[kw][6 * n1 + n2];
                #pragma unroll
                for (int k1 = 0; k1 < 8; k1++) {
                    float2 w = W8[(n1 * k1) & 7];
                    cr[k1] += q.x * w.x - q.y * w.y;
                    ci[k1] += q.x * w.y + q.y * w.x;
                }
            }
        }
        __syncthreads();                         // uniform: B2 reads done, ubuf dead
        if (act) {
            #pragma unroll
            for (int k1 = 0; k1 < 8; k1++)
                C[n2 * 8 + k1][kw] = make_float2(cr[k1], ci[k1]);
        }
    }
    __syncthreads();

    // ---- stage 4 (h, radix-6): out[k_h][k_w] --------------------------------
    {
        float xr[3][2] = {{0.f}}, xi[3][2] = {{0.f}};
        int iw[3] = {0, 0, 0};
        #pragma unroll
        for (int n2 = 0; n2 < 6; n2++) {
            int arow = n2 * 8 + k1r;
            float2 v0 = C[arow][tx];
            float2 v1 = C[arow][txg];
            #pragma unroll
            for (int a = 0; a < 3; a++) {
                float2 w = TWs[iw[a]];
                iw[a] += ty + 16 * a; if (iw[a] >= L) iw[a] -= L;
                xr[a][0] += v0.x * w.x - v0.y * w.y;
                xi[a][0] += v0.x * w.y + v0.y * w.x;
                xr[a][1] += v1.x * w.x - v1.y * w.y;
                xi[a][1] += v1.x * w.y + v1.y * w.x;
            }
        }
        float2* dst = out + (size_t)(f * L + d) * (L * LH);
        #pragma unroll
        for (int a = 0; a < 3; a++) {
            int k2 = ty + 16 * a;
            dst[(size_t)k2 * LH + tx] = make_float2(xr[a][0], xi[a][0]);
            if (g1) dst[(size_t)k2 * LH + tx + 16] = make_float2(xr[a][1], xi[a][1]);
        }
    }
}

// ============ pass D: complex, DFT along d, fold + Hermitian mirror write ===
__global__ __launch_bounds__(256, 5) void pass_d(
    const float2* __restrict__ in, float* __restrict__ out, float scale)
{
    __shared__ float2 Q2[L][LH + 1];
    __shared__ float2 A2[L][LH + 1];
    __shared__ float2 TWs[L];
    int t = threadIdx.x;
    int f = blockIdx.x / L, k2 = blockIdx.x % L;
    const float2* src = in + ((size_t)f * (L * L) + k2) * LH;

    if (t < L) TWs[t] = g_tw1[t];
    for (int idx = t; idx < L * LH; idx += 256)
        Q2[idx / LH][idx % LH] = src[(size_t)(idx / LH) * (L * LH) + (idx % LH)];
    __syncthreads();

    float2 W8[8];
    #pragma unroll
    for (int u = 0; u < 8; u++) W8[u] = TWs[6 * u];

    int tx = t & 15, ty = t >> 4;
    bool g1 = (tx < 10);
    int txg = g1 ? (tx + 16) : 0;

    // ---- stage 1 (d, complex radix-8): thread = (n2, k_w), barrier uniform --
    if (t < 6 * 26) {
        int n2 = t / 26, kw = t - n2 * 26;
        float cr[8] = {0,0,0,0,0,0,0,0}, ci[8] = {0,0,0,0,0,0,0,0};
        #pragma unroll
        for (int n1 = 0; n1 < 8; n1++) {
            float2 q = Q2[6 * n1 + n2][kw];
            #pragma unroll
            for (int k1 = 0; k1 < 8; k1++) {
                float2 w = W8[(n1 * k1) & 7];
                cr[k1] += q.x * w.x - q.y * w.y;
                ci[k1] += q.x * w.y + q.y * w.x;
            }
        }
        #pragma unroll
        for (int k1 = 0; k1 < 8; k1++)
            A2[n2 * 8 + k1][kw] = make_float2(cr[k1], ci[k1]);
    }
    __syncthreads();

    // ---- stage 2 (d, radix-6) + fold/mirror ---------------------------------
    {
        int r8 = ty & 7;
        float xr[3][2] = {{0.f}}, xi[3][2] = {{0.f}};
        int iw[3] = {0, 0, 0};
        #pragma unroll
        for (int n2 = 0; n2 < 6; n2++) {
            int arow = n2 * 8 + r8;
            float2 v0 = A2[arow][tx];
            float2 v1 = A2[arow][txg];
            #pragma unroll
            for (int a = 0; a < 3; a++) {
                float2 w = TWs[iw[a]];
                iw[a] += ty + 16 * a; if (iw[a] >= L) iw[a] -= L;
                xr[a][0] += v0.x * w.x - v0.y * w.y;
                xi[a][0] += v0.x * w.y + v0.y * w.x;
                xr[a][1] += v1.x * w.x - v1.y * w.y;
                xi[a][1] += v1.x * w.y + v1.y * w.x;
            }
        }
        int mk2 = (k2 == 0) ? 0 : L - k2;
        float* dstD = out + (size_t)f * N3 + (size_t)k2 * L;
        float* dstM = out + (size_t)f * N3 + (size_t)mk2 * L;
        int k3a = tx, k3b = tx + 16;
        int m3a = (k3a == 0) ? 0 : L - k3a;
        int m3b = L - k3b;
        #pragma unroll
        for (int a = 0; a < 3; a++) {
            int k1 = ty + 16 * a;
            int mk1 = (k1 == 0) ? 0 : L - k1;
            dstD[(size_t)k1 * 2304 + k3a]  = scale * (xr[a][0] - xi[a][0]);
            dstM[(size_t)mk1 * 2304 + m3a] = scale * (xr[a][0] + xi[a][0]);
            if (g1) {
                dstD[(size_t)k1 * 2304 + k3b]  = scale * (xr[a][1] - xi[a][1]);
                dstM[(size_t)mk1 * 2304 + m3b] = scale * (xr[a][1] + xi[a][1]);
            }
        }
    }
}

// ---------------- Y path -----------------------------------------------------
__global__ void ykernel1(const float* __restrict__ w) {
    int idx = blockIdx.x * blockDim.x + threadIdx.x;
    if (idx >= CF * 12 * 12 * L) return;
    int k3 = idx % L;
    int r  = idx / L;
    const float* wp = w + r * 12;
    float ar = 0.f, ai = 0.f;
    #pragma unroll
    for (int n3 = 0; n3 < 12; n3++) {
        float2 e = g_tw[k3 * L + n3];
        float  v = wp[n3];
        ar += v * e.x;  ai += v * e.y;
    }
    g_T1[idx] = make_float2(ar, ai);
}

// fused ykernel2 + ykernel3 (per io, quarter of k2); T1 slice in dynamic smem.
__global__ __launch_bounds__(256) void ykernel23() {
    extern __shared__ float2 ysm[];
    float2* T1s = ysm;                      // 6912 float2
    float2* T2c = ysm + 6912;               // [n1*49 + k3]
    __shared__ float2 TWs[L];
    __shared__ float2 EMPs[L];

    int t  = threadIdx.x;
    int io = blockIdx.x >> 2;
    int kt = blockIdx.x & 3;

    if (t < L) { TWs[t] = g_tw1[t]; EMPs[t] = g_emp[t]; }
    const float2* src = g_T1 + (size_t)io * 6912;
    for (int idx = t; idx < 6912; idx += 256) T1s[idx] = src[idx];
    __syncthreads();

    int tx = t & 15, ty = t >> 4;

    for (int kk = 0; kk < 12; kk++) {
        int k2 = kt * 12 + kk;

        for (int idx = t; idx < 576; idx += 256) {
            int n1 = idx / 48, k3 = idx - n1 * 48;
            const float2* tp = T1s + n1 * 576 + k3;
            float ar = 0.f, ai = 0.f;
            int iw = 0;
            #pragma unroll
            for (int n2 = 0; n2 < 12; n2++) {
                float2 v = tp[n2 * 48];
                float2 e = TWs[iw];
                iw += k2; if (iw >= L) iw -= L;
                ar += v.x * e.x - v.y * e.y;
                ai += v.x * e.y + v.y * e.x;
            }
            T2c[n1 * 49 + k3] = make_float2(ar, ai);
        }
        __syncthreads();

        {
            float acc[3][3] = {{0.f}};
            int iw2[3] = {0, 0, 0};
            #pragma unroll
            for (int n1 = 0; n1 < 12; n1++) {
                float2 tv[3];
                #pragma unroll
                for (int b = 0; b < 3; b++) tv[b] = T2c[n1 * 49 + tx + 16 * b];
                #pragma unroll
                for (int a = 0; a < 3; a++) {
                    float2 e = EMPs[iw2[a]];
                    iw2[a] += ty + 16 * a; if (iw2[a] >= L) iw2[a] -= L;
                    #pragma unroll
                    for (int b = 0; b < 3; b++)
                        acc[a][b] += tv[b].x * e.x - tv[b].y * e.y;
                }
            }
            #pragma unroll
            for (int a = 0; a < 3; a++)
                #pragma unroll
                for (int b = 0; b < 3; b++)
                    g_Yh[(size_t)io * N3 + (size_t)(ty + 16 * a) * 2304
                         + (size_t)k2 * 48 + tx + 16 * b] = acc[a][b];
        }
        __syncthreads();
    }
}

// ---------------- coalesced paired mix (MK=8, 36KB smem) ---------------------
#define MK    8
#define MPIT  12
__global__ __launch_bounds__(256) void mix3() {
    extern __shared__ float sm[];
    float* Xa = sm;                        // [128][MPIT]
    float* Xb = Xa + 128 * MPIT;
    float* Ya = Xb + 128 * MPIT;           // [256][MPIT]
    float* Yb = Ya + 256 * MPIT;

    int t  = threadIdx.x;
    int k0 = blockIdx.x * MK;

    for (int q = t; q < 128 * MK; q += 256) {
        int kk = q & 7, bi = q >> 3;
        int k = k0 + kk; if (k > NHALF) k = NHALF;
        int sk = (k == 0) ? 0 : (N3 - k);
        Xa[bi * MPIT + kk] = g_Xh[(size_t)bi * N3 + k];
        Xb[bi * MPIT + kk] = g_Xh[(size_t)bi * N3 + sk];
    }
    for (int q = t; q < 256 * MK; q += 256) {
        int kk = q & 7, io = q >> 3;
        int k = k0 + kk; if (k > NHALF) k = NHALF;
        int sk = (k == 0) ? 0 : (N3 - k);
        Ya[io * MPIT + kk] = g_Yh[(size_t)io * N3 + k];
        Yb[io * MPIT + kk] = g_Yh[(size_t)io * N3 + sk];
    }
    __syncthreads();

    int kh = t >> 7;                       // 0/1: k offset kh*4
    int b  = (t >> 4) & 7;
    int o  = t & 15;

    float acc[4] = {0,0,0,0}, accs[4] = {0,0,0,0};
    #pragma unroll 4
    for (int i = 0; i < 16; i++) {
        const float* xa = Xa + (b * 16 + i) * MPIT + kh * 4;
        const float* xb = Xb + (b * 16 + i) * MPIT + kh * 4;
        const float* ya = Ya + (i * 16 + o) * MPIT + kh * 4;
        const float* yb = Yb + (i * 16 + o) * MPIT + kh * 4;
        float xk[4], xs[4], yk[4], ys[4];
        *(float4*)&xk[0] = *(const float4*)xa;
        *(float4*)&xs[0] = *(const float4*)xb;
        *(float4*)&yk[0] = *(const float4*)ya;
        *(float4*)&ys[0] = *(const float4*)yb;
        #pragma unroll
        for (int kk = 0; kk < 4; kk++) {
            float xe = 0.5f * (xk[kk] + xs[kk]);
            float xo = 0.5f * (xk[kk] - xs[kk]);
            acc[kk]  += xe * yk[kk] + xo * ys[kk];
            accs[kk] += xe * ys[kk] - xo * yk[kk];
        }
    }

    int kb = k0 + kh * 4;
    float* zrow = g_Z + (size_t)(b * 16 + o) * N3;
    if (kb + 3 <= NHALF) {
        *(float4*)(zrow + kb) = make_float4(acc[0], acc[1], acc[2], acc[3]);
    } else {
        #pragma unroll
        for (int kk = 0; kk < 4; kk++)
            if (kb + kk <= NHALF) zrow[kb + kk] = acc[kk];
    }
    #pragma unroll
    for (int kk = 0; kk < 4; kk++) {
        int k = kb + kk;
        if (k >= 1 && k <= NHALF - 1) zrow[N3 - k] = accs[kk];
    }
}

// ---------------- launcher ----------------------------------------------------
extern "C" void kernel_launch(void* const* d_in, const int* in_sizes, int n_in,
                              void* d_out, int out_size) {
    (void)in_sizes; (void)n_in; (void)out_size;
    static float2* bufB = nullptr;
    static float*  xh   = nullptr;
    static float*  z    = nullptr;
    if (!bufB) {
        cudaGetSymbolAddress((void**)&bufB, g_bufB);
        cudaGetSymbolAddress((void**)&xh,   g_Xh);
        cudaGetSymbolAddress((void**)&z,    g_Z);
        cudaFuncSetAttribute(mix3, cudaFuncAttributeMaxDynamicSharedMemorySize,
                             (128 * MPIT * 2 + 256 * MPIT * 2) * (int)sizeof(float));
        cudaFuncSetAttribute(ykernel23, cudaFuncAttributeMaxDynamicSharedMemorySize,
                             (6912 + 12 * 49) * (int)sizeof(float2));
    }
    const float* x  = (const float*)d_in[0];   // [8,16,48,48,48]
    const float* wt = (const float*)d_in[2];   // [16,16,12,12,12]
    float* out = (float*)d_out;

    const int mix_smem = (128 * MPIT * 2 + 256 * MPIT * 2) * (int)sizeof(float);
    const int mix_grid = NHALF / MK + 1;
    const int y_smem   = (6912 + 12 * 49) * (int)sizeof(float2);

    init_tw<<<(L * L + 255) / 256, 256>>>();

    ykernel1<<<(CF * 12 * 12 * L + 255) / 256, 256>>>(wt);
    ykernel23<<<CF * 4, 256, y_smem>>>();

    // forward: x -> Xh
    pass_wh<<<BF * L, 256>>>(x, bufB);
    pass_d <<<BF * L, 256>>>(bufB, xh, 1.f);

    mix3<<<mix_grid, 256, mix_smem>>>();

    // inverse: Z -> out (scaled 1/N3)
    pass_wh<<<BF * L, 256>>>(z, bufB);
    pass_d <<<BF * L, 256>>>(bufB, out, 1.f / (float)N3);
}